// round 3
// baseline (speedup 1.0000x reference)
#include <cuda_runtime.h>
#include <cuda_bf16.h>

// Upscale_15358803050749: upfirdn2d up=2, 4x4 kernel [1,3,3,1]^2, gain 4.
// x: (8,128,128,128) f32 -> out: (8,128,256,256) f32.
//
// Polyphase (from reference's dilated conv, pad0=2):
//   out[2i]   = K[3]*x[i-1] + K[1]*x[i]
//   out[2i+1] = K[2]*x[i]   + K[0]*x[i+1]      (separably in y and x)
//
// R3: flat mapping, one thread = 4 input cols x 2 input rows.
//  - 4 independent LDG.128 issued up front (MLP=4, no loop-carried deps)
//  - horizontal halos via __shfl (warp spans one full 128-col row;
//    lane 0/31 edges are the true image boundary -> zero)
//  - produces 4 output rows x 8 cols, written as 8 aligned STG.128

#define W_IN   128
#define H_IN   128
#define W_OUT  256
#define NC     1024          // 8 * 128 planes
#define RP_PER_PLANE 64      // row-pairs per plane

// Expand float4 + shuffle halos into dst[0..5] (dst[0],dst[5] = halos).
__device__ __forceinline__ void expand_row(float* dst, float4 v, int lane,
                                           bool valid) {
    float l = __shfl_up_sync(0xffffffffu, v.w, 1);
    float r = __shfl_down_sync(0xffffffffu, v.x, 1);
    if (!valid) {
        #pragma unroll
        for (int i = 0; i < 6; i++) dst[i] = 0.f;
        return;
    }
    dst[1] = v.x; dst[2] = v.y; dst[3] = v.z; dst[4] = v.w;
    dst[0] = (lane == 0)  ? 0.f : l;
    dst[5] = (lane == 31) ? 0.f : r;
}

__global__ __launch_bounds__(256)
void Upscale_15358803050749_kernel(const float* __restrict__ x,
                                   const float* __restrict__ k,
                                   float* __restrict__ out) {
    int t    = blockIdx.x * blockDim.x + threadIdx.x;
    int lane = t & 31;                      // column group (4 cols each)
    int rp   = t >> 5;                      // global row-pair index
    int iy0  = (rp & (RP_PER_PLANE - 1)) * 2;
    int pl   = rp >> 6;                     // plane 0..NC-1
    int ix0  = lane * 4;

    const float* xp = x   + (size_t)pl * (H_IN * W_IN);
    float*       op = out + (size_t)pl * (256 * W_OUT);

    float K00 = __ldg(k + 0),  K01 = __ldg(k + 1),  K02 = __ldg(k + 2),  K03 = __ldg(k + 3);
    float K10 = __ldg(k + 4),  K11 = __ldg(k + 5),  K12 = __ldg(k + 6),  K13 = __ldg(k + 7);
    float K20 = __ldg(k + 8),  K21 = __ldg(k + 9),  K22 = __ldg(k + 10), K23 = __ldg(k + 11);
    float K30 = __ldg(k + 12), K31 = __ldg(k + 13), K32 = __ldg(k + 14), K33 = __ldg(k + 15);

    // 4 independent row loads: iy0-1, iy0, iy0+1, iy0+2.
    bool v0 = (iy0 > 0);
    bool v3 = (iy0 + 2 < H_IN);
    // clamp row index so the (predicated-dead) load address stays in bounds
    const float* p0 = xp + (size_t)(v0 ? iy0 - 1 : 0) * W_IN + ix0;
    const float* p1 = xp + (size_t)iy0 * W_IN + ix0;
    const float* p2 = xp + (size_t)(iy0 + 1) * W_IN + ix0;
    const float* p3 = xp + (size_t)(v3 ? iy0 + 2 : 0) * W_IN + ix0;

    float4 v0v = *reinterpret_cast<const float4*>(p0);
    float4 v1v = *reinterpret_cast<const float4*>(p1);
    float4 v2v = *reinterpret_cast<const float4*>(p2);
    float4 v3v = *reinterpret_cast<const float4*>(p3);

    float r0[6], r1[6], r2[6], r3[6];
    expand_row(r0, v0v, lane, v0);
    expand_row(r1, v1v, lane, true);
    expand_row(r2, v2v, lane, true);
    expand_row(r3, v3v, lane, v3);

    // Two output row-pairs: (a,b,c) = (r0,r1,r2) then (r1,r2,r3).
    #pragma unroll
    for (int i = 0; i < 2; i++) {
        const float* a = (i == 0) ? r0 : r1;
        const float* b = (i == 0) ? r1 : r2;
        const float* c = (i == 0) ? r2 : r3;
        int iy = iy0 + i;

        float oe[8], oo[8];
        #pragma unroll
        for (int j = 0; j < 4; j++) {
            int lj = j + 1;
            // out row 2*iy   (even vert phase: K[3]*row(iy-1) + K[1]*row(iy))
            oe[2*j]     = K33 * a[lj-1] + K31 * a[lj]
                        + K13 * b[lj-1] + K11 * b[lj];
            oe[2*j + 1] = K32 * a[lj]   + K30 * a[lj+1]
                        + K12 * b[lj]   + K10 * b[lj+1];
            // out row 2*iy+1 (odd vert phase: K[2]*row(iy) + K[0]*row(iy+1))
            oo[2*j]     = K23 * b[lj-1] + K21 * b[lj]
                        + K03 * c[lj-1] + K01 * c[lj];
            oo[2*j + 1] = K22 * b[lj]   + K20 * b[lj+1]
                        + K02 * c[lj]   + K00 * c[lj+1];
        }

        int ox0 = 2 * ix0;   // multiple of 8 -> aligned float4 stores
        float* oe_p = op + (size_t)(2 * iy) * W_OUT + ox0;
        float* oo_p = op + (size_t)(2 * iy + 1) * W_OUT + ox0;
        *reinterpret_cast<float4*>(oe_p)     = make_float4(oe[0], oe[1], oe[2], oe[3]);
        *reinterpret_cast<float4*>(oe_p + 4) = make_float4(oe[4], oe[5], oe[6], oe[7]);
        *reinterpret_cast<float4*>(oo_p)     = make_float4(oo[0], oo[1], oo[2], oo[3]);
        *reinterpret_cast<float4*>(oo_p + 4) = make_float4(oo[4], oo[5], oo[6], oo[7]);
    }
}

extern "C" void kernel_launch(void* const* d_in, const int* in_sizes, int n_in,
                              void* d_out, int out_size) {
    const float* x = (const float*)d_in[0];   // (8,128,128,128)
    const float* k = (const float*)d_in[1];   // (4,4)
    float* out = (float*)d_out;               // (8,128,256,256)

    // warps = NC * 64 row-pairs = 65536 ; threads = 2,097,152
    int threads = 256;
    int blocks = (NC * RP_PER_PLANE * 32) / threads;  // 8192
    Upscale_15358803050749_kernel<<<blocks, threads>>>(x, k, out);
}

// round 4
// speedup vs baseline: 1.4535x; 1.4535x over previous
#include <cuda_runtime.h>
#include <cuda_bf16.h>

// Upscale_15358803050749: upfirdn2d up=2, 4x4 kernel [1,3,3,1]^2, gain 4.
// x: (8,128,128,128) f32 -> out: (8,128,256,256) f32.
//
// Polyphase (from reference's dilated conv, pad0=2), separably factored:
//   K[v][u] = C[v] * D[u],  D[u] = K[0][u],  C[v] = K[v][0] / K[0][0]
//   horizontal: he[j] = D3*x[j-1] + D1*x[j] ; ho[j] = D2*x[j] + D0*x[j+1]
//   vertical  : out_even = C3*H(iy-1) + C1*H(iy)
//               out_odd  = C2*H(iy)   + C0*H(iy+1)
//
// R4: one warp = 8-input-row strip, lane = 4 input cols. Rolling register
// buffers hold the horizontally-transformed rows (8 floats). NO SHFL
// (proved ~MUFU-rate on sm_103a; R2/R3 regressions). Halos via 2 scalar
// LDG (L1/L2 hits). Streaming stores keep the input resident in L2.

#define W_IN   128
#define H_IN   128
#define W_OUT  256
#define NC     1024          // 8 * 128 planes
#define ROWS   8             // input rows per warp strip
#define STRIPS (H_IN / ROWS) // 16

// Load one raw input row segment and horizontally transform into dst[0..7]
// (dst = the 8 output columns' horizontal partials, in output order).
__device__ __forceinline__ void load_htrans(float* dst, const float* __restrict__ rowp,
                                            int ix0,
                                            float D0, float D1, float D2, float D3) {
    float4 v = *reinterpret_cast<const float4*>(rowp + ix0);
    float xl = (ix0 > 0)        ? __ldg(rowp + ix0 - 1) : 0.f;
    float xr = (ix0 + 4 < W_IN) ? __ldg(rowp + ix0 + 4) : 0.f;
    float x0 = xl, x1 = v.x, x2 = v.y, x3 = v.z, x4 = v.w, x5 = xr;
    dst[0] = D3 * x0 + D1 * x1;   dst[1] = D2 * x1 + D0 * x2;
    dst[2] = D3 * x1 + D1 * x2;   dst[3] = D2 * x2 + D0 * x3;
    dst[4] = D3 * x2 + D1 * x3;   dst[5] = D2 * x3 + D0 * x4;
    dst[6] = D3 * x3 + D1 * x4;   dst[7] = D2 * x4 + D0 * x5;
}

__device__ __forceinline__ void zero8(float* dst) {
    #pragma unroll
    for (int i = 0; i < 8; i++) dst[i] = 0.f;
}

__global__ __launch_bounds__(256)
void Upscale_15358803050749_kernel(const float* __restrict__ x,
                                   const float* __restrict__ k,
                                   float* __restrict__ out) {
    int gw    = (blockIdx.x * blockDim.x + threadIdx.x) >> 5;
    int lane  = threadIdx.x & 31;
    int strip = gw & (STRIPS - 1);
    int pl    = gw >> 4;                 // plane 0..NC-1
    int iy0   = strip * ROWS;
    int ix0   = lane * 4;

    const float* xp = x   + (size_t)pl * (H_IN * W_IN);
    float*       op = out + (size_t)pl * (256 * W_OUT);

    // Separable factors (exact up to f32 rounding for outer-product kernels).
    float D0 = __ldg(k + 0), D1 = __ldg(k + 1), D2 = __ldg(k + 2), D3 = __ldg(k + 3);
    float invK00 = 1.0f / D0;
    float C0 = 1.0f;                      // k[0]/k[0]
    float C1 = __ldg(k + 4)  * invK00;
    float C2 = __ldg(k + 8)  * invK00;
    float C3 = __ldg(k + 12) * invK00;

    // Rolling h-transformed row buffers: A = H(iy-1), B = H(iy), C = H(iy+1).
    float A[8], B[8], C[8];
    if (iy0 > 0) load_htrans(A, xp + (size_t)(iy0 - 1) * W_IN, ix0, D0, D1, D2, D3);
    else         zero8(A);
    load_htrans(B, xp + (size_t)iy0 * W_IN, ix0, D0, D1, D2, D3);

    int ox0 = 2 * ix0;   // multiple of 8 -> aligned float4 stores

    #pragma unroll
    for (int i = 0; i < ROWS; i++) {
        int iy  = iy0 + i;
        int iyn = iy + 1;
        if (iyn < H_IN) load_htrans(C, xp + (size_t)iyn * W_IN, ix0, D0, D1, D2, D3);
        else            zero8(C);

        float oe[8], oo[8];
        #pragma unroll
        for (int u = 0; u < 8; u++) {
            oe[u] = C3 * A[u] + C1 * B[u];   // even output row 2*iy
            oo[u] = C2 * B[u] + C0 * C[u];   // odd  output row 2*iy+1
        }

        float* oe_p = op + (size_t)(2 * iy) * W_OUT + ox0;
        float* oo_p = op + (size_t)(2 * iy + 1) * W_OUT + ox0;
        __stcs(reinterpret_cast<float4*>(oe_p),     make_float4(oe[0], oe[1], oe[2], oe[3]));
        __stcs(reinterpret_cast<float4*>(oe_p + 4), make_float4(oe[4], oe[5], oe[6], oe[7]));
        __stcs(reinterpret_cast<float4*>(oo_p),     make_float4(oo[0], oo[1], oo[2], oo[3]));
        __stcs(reinterpret_cast<float4*>(oo_p + 4), make_float4(oo[4], oo[5], oo[6], oo[7]));

        // roll buffers (renamed away by full unroll)
        #pragma unroll
        for (int q = 0; q < 8; q++) { A[q] = B[q]; B[q] = C[q]; }
    }
}

extern "C" void kernel_launch(void* const* d_in, const int* in_sizes, int n_in,
                              void* d_out, int out_size) {
    const float* x = (const float*)d_in[0];   // (8,128,128,128)
    const float* k = (const float*)d_in[1];   // (4,4)
    float* out = (float*)d_out;               // (8,128,256,256)

    // warps = NC * STRIPS = 16384 ; threads = 524288 ; blocks = 2048
    int threads = 256;
    int blocks = (NC * STRIPS * 32) / threads;
    Upscale_15358803050749_kernel<<<blocks, threads>>>(x, k, out);
}

// round 6
// speedup vs baseline: 1.4986x; 1.0311x over previous
#include <cuda_runtime.h>
#include <cuda_bf16.h>

// Upscale_15358803050749: upfirdn2d up=2, 4x4 kernel [1,3,3,1]^2, gain 4.
// x: (8,128,128,128) f32 -> out: (8,128,256,256) f32.
//
// Polyphase (from reference's dilated conv, pad0=2), separably factored:
//   K[v][u] = C[v]*D[u],  D[u]=K[0][u],  C[v]=K[v][0]/K[0][0]
//   horiz: He[j] = D3*x[j-1] + D1*x[j] ; Ho[j] = D2*x[j] + D0*x[j+1]
//   vert : out_even(2i)  = C3*H(i-1) + C1*H(i)
//          out_odd (2i+1)= C2*H(i)   + C0*H(i+1),  C0 == 1
//
// R6 = R5 with the coverage bug fixed: one thread = 2 input rows, so a
// 128-row plane needs 64 thread-rows (DRP=64), not 32. FLAT mapping
// (no rolling, no shfl — both proven losers on sm_103a). All 12 LDGs
// independent, issued up front (MLP=12). Streaming stores protect the
// 64MB input's L2 residency.

#define W_IN   128
#define H_IN   128
#define W_OUT  256
#define NC     1024          // 8 * 128 planes
#define DRP    64            // double-rows per plane (2 input rows each)

__global__ __launch_bounds__(256)
void Upscale_15358803050749_kernel(const float* __restrict__ x,
                                   const float* __restrict__ k,
                                   float* __restrict__ out) {
    int t    = blockIdx.x * blockDim.x + threadIdx.x;
    int lane = t & 31;                    // column group (4 cols each)
    int rp   = t >> 5;
    int ry   = rp & (DRP - 1);
    int pl   = rp >> 6;                   // plane 0..NC-1
    int iy0  = ry * 2;                    // first input row of this thread
    int ix0  = lane * 4;

    const float* xp = x   + pl * (H_IN * W_IN);   // fits in 32-bit math
    float*       op = out + pl * (256 * W_OUT);

    // ---- 12 independent loads, issued before any dependent compute ----
    bool vm = (iy0 > 0);
    bool vc = (iy0 + 2 < H_IN);
    const float* pm = xp + (vm ? (iy0 - 1) * W_IN : 0) + ix0;
    const float* pa = xp + iy0 * W_IN + ix0;
    const float* pb = xp + (iy0 + 1) * W_IN + ix0;
    const float* pc = xp + (vc ? (iy0 + 2) * W_IN : 0) + ix0;

    float4 vmv = *reinterpret_cast<const float4*>(pm);
    float4 vav = *reinterpret_cast<const float4*>(pa);
    float4 vbv = *reinterpret_cast<const float4*>(pb);
    float4 vcv = *reinterpret_cast<const float4*>(pc);

    bool hl = (ix0 > 0);
    bool hr = (ix0 + 4 < W_IN);
    float lm = hl ? __ldg(pm - 1) : 0.f;
    float la = hl ? __ldg(pa - 1) : 0.f;
    float lb = hl ? __ldg(pb - 1) : 0.f;
    float lc = hl ? __ldg(pc - 1) : 0.f;
    float rm = hr ? __ldg(pm + 4) : 0.f;
    float ra = hr ? __ldg(pa + 4) : 0.f;
    float rb = hr ? __ldg(pb + 4) : 0.f;
    float rc = hr ? __ldg(pc + 4) : 0.f;

    // ---- separable factors ----
    float D0 = __ldg(k + 0), D1 = __ldg(k + 1), D2 = __ldg(k + 2), D3 = __ldg(k + 3);
    float inv = 1.0f / D0;
    float C1 = __ldg(k + 4)  * inv;
    float C2 = __ldg(k + 8)  * inv;
    float C3 = __ldg(k + 12) * inv;     // C0 == 1

    if (!vm) { vmv = make_float4(0.f,0.f,0.f,0.f); lm = 0.f; rm = 0.f; }
    if (!vc) { vcv = make_float4(0.f,0.f,0.f,0.f); lc = 0.f; rc = 0.f; }

    // ---- horizontal transform: row -> 8 output-column partials ----
    float Hm[8], Ha[8], Hb[8], Hc[8];
    #define HT(H, L, V, R)                                        \
        H[0] = D3*(L)   + D1*(V).x;  H[1] = D2*(V).x + D0*(V).y;  \
        H[2] = D3*(V).x + D1*(V).y;  H[3] = D2*(V).y + D0*(V).z;  \
        H[4] = D3*(V).y + D1*(V).z;  H[5] = D2*(V).z + D0*(V).w;  \
        H[6] = D3*(V).z + D1*(V).w;  H[7] = D2*(V).w + D0*(R);
    HT(Hm, lm, vmv, rm)
    HT(Ha, la, vav, ra)
    HT(Hb, lb, vbv, rb)
    HT(Hc, lc, vcv, rc)
    #undef HT

    // ---- vertical combine: 4 output rows ----
    float o0[8], o1[8], o2[8], o3[8];
    #pragma unroll
    for (int u = 0; u < 8; u++) {
        o0[u] = C3 * Hm[u] + C1 * Ha[u];   // row 2*iy0
        o1[u] = C2 * Ha[u] + Hb[u];        // row 2*iy0+1 (C0=1)
        o2[u] = C3 * Ha[u] + C1 * Hb[u];   // row 2*iy0+2
        o3[u] = C2 * Hb[u] + Hc[u];        // row 2*iy0+3
    }

    int ox0 = 2 * ix0;                      // multiple of 8 -> aligned
    float* q = op + (2 * iy0) * W_OUT + ox0;
    __stcs(reinterpret_cast<float4*>(q),                 make_float4(o0[0],o0[1],o0[2],o0[3]));
    __stcs(reinterpret_cast<float4*>(q + 4),             make_float4(o0[4],o0[5],o0[6],o0[7]));
    __stcs(reinterpret_cast<float4*>(q + W_OUT),         make_float4(o1[0],o1[1],o1[2],o1[3]));
    __stcs(reinterpret_cast<float4*>(q + W_OUT + 4),     make_float4(o1[4],o1[5],o1[6],o1[7]));
    __stcs(reinterpret_cast<float4*>(q + 2*W_OUT),       make_float4(o2[0],o2[1],o2[2],o2[3]));
    __stcs(reinterpret_cast<float4*>(q + 2*W_OUT + 4),   make_float4(o2[4],o2[5],o2[6],o2[7]));
    __stcs(reinterpret_cast<float4*>(q + 3*W_OUT),       make_float4(o3[0],o3[1],o3[2],o3[3]));
    __stcs(reinterpret_cast<float4*>(q + 3*W_OUT + 4),   make_float4(o3[4],o3[5],o3[6],o3[7]));
}

extern "C" void kernel_launch(void* const* d_in, const int* in_sizes, int n_in,
                              void* d_out, int out_size) {
    const float* x = (const float*)d_in[0];   // (8,128,128,128)
    const float* k = (const float*)d_in[1];   // (4,4)
    float* out = (float*)d_out;               // (8,128,256,256)

    // threads = NC * DRP * 32 = 2,097,152 ; blocks = 8192
    int threads = 256;
    int blocks = (NC * DRP * 32) / threads;
    Upscale_15358803050749_kernel<<<blocks, threads>>>(x, k, out);
}

// round 7
// speedup vs baseline: 1.6113x; 1.0752x over previous
#include <cuda_runtime.h>
#include <cuda_bf16.h>

// Upscale_15358803050749: upfirdn2d up=2, 4x4 kernel [1,3,3,1]^2, gain 4.
// x: (8,128,128,128) f32 -> out: (8,128,256,256) f32.
//
// Polyphase (reference's dilated conv, pad0=2), separably factored:
//   K[v][u] = C[v]*D[u],  D[u]=K[0][u],  C[v]=K[v][0]/K[0][0]  (C0==1)
//   horiz: out col 2i   = D3*x[i-1] + D1*x[i]
//          out col 2i+1 = D2*x[i]   + D0*x[i+1]
//   vert : out row 2r   = C3*H(r-1) + C1*H(r)
//          out row 2r+1 = C2*H(r)   + C0*H(r+1)
//
// R7: NO scalar halo loads. Each thread loads two float4 per row:
//   V @ ix0, U @ (ix0+4)&127   (lane 31 wraps to col 0 -> warp's U loads
//   still cover one full 512B line, perfectly coalesced).
// Output window shifted to [8l+4 .. 8l+11] (16B aligned). Lane 31's second
// float4 wraps to output cols [0..3]; correctness there requires exactly
// V.w -> 0 (for the "x[128]" term) and U.x -> 0 (for the x[128] in the odd
// col 255) — two selects per row, no divergent loads.
// Per-warp L1 wavefronts: 64 (was 80 in R6).

#define W_IN   128
#define H_IN   128
#define W_OUT  256
#define NC     1024          // 8 * 128 planes
#define DRP    64            // thread-rows per plane (2 input rows each)

__global__ __launch_bounds__(256)
void Upscale_15358803050749_kernel(const float* __restrict__ x,
                                   const float* __restrict__ k,
                                   float* __restrict__ out) {
    int t    = blockIdx.x * blockDim.x + threadIdx.x;
    int lane = t & 31;
    int rp   = t >> 5;
    int ry   = rp & (DRP - 1);
    int pl   = rp >> 6;                   // plane 0..NC-1
    int iy0  = ry * 2;                    // first input row of this thread
    int ix0  = lane * 4;
    int ixu  = (ix0 + 4) & (W_IN - 1);    // wrapped halo-vector column

    const float* xp = x   + pl * (H_IN * W_IN);
    float*       op = out + pl * (256 * W_OUT);

    // ---- 8 independent vector loads (MLP=8), no scalar loads ----
    bool vm = (iy0 > 0);
    bool vc = (iy0 + 2 < H_IN);
    const float* rm_p = xp + (vm ? (iy0 - 1) * W_IN : 0);
    const float* ra_p = xp + iy0 * W_IN;
    const float* rb_p = xp + (iy0 + 1) * W_IN;
    const float* rc_p = xp + (vc ? (iy0 + 2) * W_IN : 0);

    float4 Vm = *reinterpret_cast<const float4*>(rm_p + ix0);
    float4 Um = *reinterpret_cast<const float4*>(rm_p + ixu);
    float4 Va = *reinterpret_cast<const float4*>(ra_p + ix0);
    float4 Ua = *reinterpret_cast<const float4*>(ra_p + ixu);
    float4 Vb = *reinterpret_cast<const float4*>(rb_p + ix0);
    float4 Ub = *reinterpret_cast<const float4*>(rb_p + ixu);
    float4 Vc = *reinterpret_cast<const float4*>(rc_p + ix0);
    float4 Uc = *reinterpret_cast<const float4*>(rc_p + ixu);

    // ---- separable factors ----
    float D0 = __ldg(k + 0), D1 = __ldg(k + 1), D2 = __ldg(k + 2), D3 = __ldg(k + 3);
    float inv = 1.0f / D0;
    float C1 = __ldg(k + 4)  * inv;
    float C2 = __ldg(k + 8)  * inv;
    float C3 = __ldg(k + 12) * inv;     // C0 == 1

    float4 Z = make_float4(0.f, 0.f, 0.f, 0.f);
    if (!vm) { Vm = Z; Um = Z; }
    if (!vc) { Vc = Z; Uc = Z; }
    bool last = (lane == 31);            // wrap lane: mask x[128] terms

    // ---- horizontal transform: (V,U) -> 8 partials for out cols [8l+4..8l+11]
    float Hm[8], Ha[8], Hb[8], Hc[8];
    #define HT(H, V, U)                                                   \
    {                                                                     \
        float Vwz = last ? 0.f : (V).w;                                   \
        float Uxz = last ? 0.f : (U).x;                                   \
        H[0] = D3*(V).y + D1*(V).z;   /* c+0 even, i=4l+2 */              \
        H[1] = D2*(V).z + D0*(V).w;   /* c+1 odd         */              \
        H[2] = D3*(V).z + D1*(V).w;   /* c+2 even, i=4l+3 */              \
        H[3] = D2*(V).w + D0*Uxz;     /* c+3 odd  (x[4l+4]; 0 at wrap) */ \
        H[4] = D3*Vwz   + D1*(U).x;   /* c+4 even (x[4l+3]; 0 at wrap) */ \
        H[5] = D2*(U).x + D0*(U).y;   /* c+5 odd         */              \
        H[6] = D3*(U).x + D1*(U).y;   /* c+6 even        */              \
        H[7] = D2*(U).y + D0*(U).z;   /* c+7 odd         */              \
    }
    HT(Hm, Vm, Um)
    HT(Ha, Va, Ua)
    HT(Hb, Vb, Ub)
    HT(Hc, Vc, Uc)
    #undef HT

    // ---- vertical combine: 4 output rows ----
    float o0[8], o1[8], o2[8], o3[8];
    #pragma unroll
    for (int u = 0; u < 8; u++) {
        o0[u] = C3 * Hm[u] + C1 * Ha[u];   // row 2*iy0
        o1[u] = C2 * Ha[u] + Hb[u];        // row 2*iy0+1 (C0=1)
        o2[u] = C3 * Ha[u] + C1 * Hb[u];   // row 2*iy0+2
        o3[u] = C2 * Hb[u] + Hc[u];        // row 2*iy0+3
    }

    // ---- stores: two aligned float4 per row; second wraps for lane 31 ----
    int cA = 8 * lane + 4;                 // cols [8l+4..8l+7]
    int cB = (8 * lane + 8) & (W_OUT - 1); // cols [8l+8..8l+11] (lane31 -> 0..3)
    float* q0 = op + (2 * iy0) * W_OUT;
    float* q1 = q0 + W_OUT;
    float* q2 = q1 + W_OUT;
    float* q3 = q2 + W_OUT;
    __stcs(reinterpret_cast<float4*>(q0 + cA), make_float4(o0[0],o0[1],o0[2],o0[3]));
    __stcs(reinterpret_cast<float4*>(q0 + cB), make_float4(o0[4],o0[5],o0[6],o0[7]));
    __stcs(reinterpret_cast<float4*>(q1 + cA), make_float4(o1[0],o1[1],o1[2],o1[3]));
    __stcs(reinterpret_cast<float4*>(q1 + cB), make_float4(o1[4],o1[5],o1[6],o1[7]));
    __stcs(reinterpret_cast<float4*>(q2 + cA), make_float4(o2[0],o2[1],o2[2],o2[3]));
    __stcs(reinterpret_cast<float4*>(q2 + cB), make_float4(o2[4],o2[5],o2[6],o2[7]));
    __stcs(reinterpret_cast<float4*>(q3 + cA), make_float4(o3[0],o3[1],o3[2],o3[3]));
    __stcs(reinterpret_cast<float4*>(q3 + cB), make_float4(o3[4],o3[5],o3[6],o3[7]));
}

extern "C" void kernel_launch(void* const* d_in, const int* in_sizes, int n_in,
                              void* d_out, int out_size) {
    const float* x = (const float*)d_in[0];   // (8,128,128,128)
    const float* k = (const float*)d_in[1];   // (4,4)
    float* out = (float*)d_out;               // (8,128,256,256)

    // threads = NC * DRP * 32 = 2,097,152 ; blocks = 8192
    int threads = 256;
    int blocks = (NC * DRP * 32) / threads;
    Upscale_15358803050749_kernel<<<blocks, threads>>>(x, k, out);
}